// round 9
// baseline (speedup 1.0000x reference)
#include <cuda_runtime.h>

// Time2Vec: out[b,l,d*64+e] = (e==0) ? x*W[d,0]+b[d,0] : sin(x*W[d,e]+b[d,e])
// x: (32,4096,8) fp32, W/b: (8,64) fp32, out: (32,4096,512) fp32 = 16,777,216 quads.
//
// Converged design: write-stream kernel near the HBM write floor. Winning
// regime (R4->R8 gradient): MANY short-lived dense blocks — HW block
// replacement supplies inter-tile MLP and overlaps store-drain tails.
// ITER 8->4 won (45.2->44.1us, DRAM 65.8%); this round ITER=2 (8KB tiles,
// 32768 blocks). (d,e) and w4/b4 stay loop-invariant registers.

constexpr int N_QUADS     = 1 << 24;                 // 16,777,216
constexpr int THREADS     = 256;
constexpr int ITER        = 2;
constexpr int BLOCK_QUADS = THREADS * ITER;          // 512 quads = 8 KB contiguous
constexpr int BLOCKS      = N_QUADS / BLOCK_QUADS;   // 32768
constexpr int XITER       = THREADS / 16;            // 16 x-elements per iter step

__global__ __launch_bounds__(THREADS, 8)
void time2vec_kernel(const float* __restrict__ x,
                     const float* __restrict__ W,
                     const float* __restrict__ B,
                     float4* __restrict__ out)
{
    const int q0 = blockIdx.x * BLOCK_QUADS + threadIdx.x;

    // loop-invariant coordinates (block offset mult of 512, per-iter stride
    // 256 — both multiples of 128 quads -> (d,e) depend only on tid)
    const int e = (q0 & 15) << 2;        // starting e within [0,64)
    const int d = (q0 >> 4) & 7;         // D = 8
    const bool first = (e == 0);         // passthrough lane

    const float4 w4 = __ldg((const float4*)(W + d * 64 + e));
    const float4 b4 = __ldg((const float4*)(B + d * 64 + e));

    const int x0 = q0 >> 4;

    // front-batch the streaming x loads (each read exactly once)
    float xv[ITER];
    #pragma unroll
    for (int i = 0; i < ITER; i++)
        xv[i] = __ldcs(&x[x0 + i * XITER]);

    #pragma unroll
    for (int i = 0; i < ITER; i++) {
        const float v0 = fmaf(xv[i], w4.x, b4.x);
        float4 r;
        r.x = first ? v0 : __sinf(v0);
        r.y = __sinf(fmaf(xv[i], w4.y, b4.y));
        r.z = __sinf(fmaf(xv[i], w4.z, b4.z));
        r.w = __sinf(fmaf(xv[i], w4.w, b4.w));

        __stcs(&out[q0 + i * THREADS], r);   // dense 8KB per block
    }
}

extern "C" void kernel_launch(void* const* d_in, const int* in_sizes, int n_in,
                              void* d_out, int out_size)
{
    const float* x = (const float*)d_in[0];
    const float* W = (const float*)d_in[1];
    const float* B = (const float*)d_in[2];
    time2vec_kernel<<<BLOCKS, THREADS>>>(x, W, B, (float4*)d_out);
}

// round 10
// speedup vs baseline: 1.1001x; 1.1001x over previous
#include <cuda_runtime.h>

// Time2Vec: out[b,l,d*64+e] = (e==0) ? x*W[d,0]+b[d,0] : sin(x*W[d,e]+b[d,e])
// x: (32,4096,8) fp32, W/b: (8,64) fp32, out: (32,4096,512) fp32 = 16,777,216 quads.
//
// Best-known structure (R8: ITER=4, 16KB dense tiles, 16384 blocks, 44.1us,
// DRAM 65.8%). This round's single change: st.global.wt (write-through)
// instead of .cs — probing whether skipping the L2 dirty-line writeback
// transit lifts the ~5.2TB/s store ceiling. Everything else identical.

constexpr int N_QUADS     = 1 << 24;                 // 16,777,216
constexpr int THREADS     = 256;
constexpr int ITER        = 4;
constexpr int BLOCK_QUADS = THREADS * ITER;          // 1024 quads = 16 KB contiguous
constexpr int BLOCKS      = N_QUADS / BLOCK_QUADS;   // 16384
constexpr int XITER       = THREADS / 16;            // 16 x-elements per iter step

__global__ __launch_bounds__(THREADS, 8)
void time2vec_kernel(const float* __restrict__ x,
                     const float* __restrict__ W,
                     const float* __restrict__ B,
                     float4* __restrict__ out)
{
    const int q0 = blockIdx.x * BLOCK_QUADS + threadIdx.x;

    // loop-invariant coordinates (block offset mult of 1024, per-iter stride
    // 256 — both multiples of 128 quads -> (d,e) depend only on tid)
    const int e = (q0 & 15) << 2;        // starting e within [0,64)
    const int d = (q0 >> 4) & 7;         // D = 8
    const bool first = (e == 0);         // passthrough lane

    const float4 w4 = __ldg((const float4*)(W + d * 64 + e));
    const float4 b4 = __ldg((const float4*)(B + d * 64 + e));

    const int x0 = q0 >> 4;

    // front-batch the streaming x loads (each read exactly once)
    float xv[ITER];
    #pragma unroll
    for (int i = 0; i < ITER; i++)
        xv[i] = __ldcs(&x[x0 + i * XITER]);

    #pragma unroll
    for (int i = 0; i < ITER; i++) {
        const float v0 = fmaf(xv[i], w4.x, b4.x);
        float4 r;
        r.x = first ? v0 : __sinf(v0);
        r.y = __sinf(fmaf(xv[i], w4.y, b4.y));
        r.z = __sinf(fmaf(xv[i], w4.z, b4.z));
        r.w = __sinf(fmaf(xv[i], w4.w, b4.w));

        __stwt(&out[q0 + i * THREADS], r);   // write-through: no L2 writeback transit
    }
}

extern "C" void kernel_launch(void* const* d_in, const int* in_sizes, int n_in,
                              void* d_out, int out_size)
{
    const float* x = (const float*)d_in[0];
    const float* W = (const float*)d_in[1];
    const float* B = (const float*)d_in[2];
    time2vec_kernel<<<BLOCKS, THREADS>>>(x, W, B, (float4*)d_out);
}